// round 16
// baseline (speedup 1.0000x reference)
#include <cuda_runtime.h>
#include <cuda_bf16.h>
#include <math.h>
#include <stdint.h>

// NTXent — Round 16: R15 + halved barrier count in hmma.
//  hmma: 128x128 CTA, 4 warps of 64x64, BK=32, 4 stages, TWO stages computed
//        per wait_group/syncthreads (10 barriers instead of 20), refill AFTER
//        compute. prep/finalize/zeroq: R15 verbatim.

#define B_SIZE 8192
#define D_SIZE 626
#define D2     313
#define KPAD   640
#define INV_TEMP 4.0f

#define BM 128
#define BN 128
#define BK 32
#define NITER (KPAD / BK)             // 20 BK-blocks
#define NHALF (NITER / 2)             // 10 loop iterations
#define STAGES 4
#define ROWB 80                        // 32 bf16 + 8B pad
#define STAGE_BYTES (2 * BM * ROWB)    // 20480
#define SMEM_BYTES (STAGES * STAGE_BYTES)   // 81920

// ---------------- persistent scratch ---------------------------------------
__device__ __align__(128) __nv_bfloat16 g_Ab[B_SIZE * KPAD];
__device__ __align__(128) __nv_bfloat16 g_Pb[B_SIZE * KPAD];
__device__ float g_rna[B_SIZE];
__device__ float g_sumexp[B_SIZE];
__device__ float g_diag[B_SIZE];
__device__ __align__(8) float g_q[KPAD];

// ---------------- helpers ---------------------------------------------------
__device__ __forceinline__ uint32_t smem_u32(const void* p) {
    uint32_t a;
    asm("{ .reg .u64 t; cvta.to.shared.u64 t, %1; cvt.u32.u64 %0, t; }"
        : "=r"(a) : "l"(p));
    return a;
}
__device__ __forceinline__ void cp16(uint32_t dst, const void* src) {
    asm volatile("cp.async.cg.shared.global [%0], [%1], 16;" :: "r"(dst), "l"(src));
}
__device__ __forceinline__ void ldsm_x4(uint32_t* r, uint32_t addr) {
    asm volatile("ldmatrix.sync.aligned.m8n8.x4.shared.b16 {%0,%1,%2,%3}, [%4];"
                 : "=r"(r[0]), "=r"(r[1]), "=r"(r[2]), "=r"(r[3]) : "r"(addr));
}
__device__ __forceinline__ void mma_bf16(float* c, const uint32_t* a,
                                         uint32_t b0, uint32_t b1) {
    asm volatile(
        "mma.sync.aligned.m16n8k16.row.col.f32.bf16.bf16.f32 "
        "{%0,%1,%2,%3}, {%4,%5,%6,%7}, {%8,%9}, {%0,%1,%2,%3};"
        : "+f"(c[0]), "+f"(c[1]), "+f"(c[2]), "+f"(c[3])
        : "r"(a[0]), "r"(a[1]), "r"(a[2]), "r"(a[3]), "r"(b0), "r"(b1));
}

// ---------------------------------------------------------------------------
// zeroq
// ---------------------------------------------------------------------------
__global__ void ntxent_zeroq() {
    if (threadIdx.x < KPAD) g_q[threadIdx.x] = 0.f;
}

// ---------------------------------------------------------------------------
// prep (R13/R15 verbatim): norms, exact fp32 diag, normalized bf16 copies,
// fused q accumulation. grid B/8, block 256; one warp per row.
// ---------------------------------------------------------------------------
__global__ void __launch_bounds__(256) ntxent_prep(const float* __restrict__ A,
                                                   const float* __restrict__ P,
                                                   float* __restrict__ out) {
    __shared__ float qacc[D_SIZE];
    for (int c = threadIdx.x; c < D_SIZE; c += 256) qacc[c] = 0.f;
    __syncthreads();

    const int warp = threadIdx.x >> 5;
    const int lane = threadIdx.x & 31;
    const int row  = blockIdx.x * 8 + warp;

    const float* ar = A + (size_t)row * D_SIZE;
    const float* pr = P + (size_t)row * D_SIZE;
    float ssa = 0.f, ssp = 0.f, dot = 0.f;
    for (int c = lane; c < D_SIZE; c += 32) {
        float av = ar[c], pv = pr[c];
        ssa = fmaf(av, av, ssa);
        ssp = fmaf(pv, pv, ssp);
        dot = fmaf(av, pv, dot);
    }
    #pragma unroll
    for (int o = 16; o; o >>= 1) {
        ssa += __shfl_xor_sync(0xffffffffu, ssa, o);
        ssp += __shfl_xor_sync(0xffffffffu, ssp, o);
        dot += __shfl_xor_sync(0xffffffffu, dot, o);
    }
    const float rna = rsqrtf(ssa);
    const float rnp = rsqrtf(ssp);

    __nv_bfloat16* ya = g_Ab + (size_t)row * KPAD;
    __nv_bfloat16* yp = g_Pb + (size_t)row * KPAD;
    for (int c = lane; c < KPAD; c += 32) {
        float av = (c < D_SIZE) ? ar[c] * rna : 0.f;
        float pv = (c < D_SIZE) ? pr[c] * rnp : 0.f;
        ya[c] = __float2bfloat16(av);
        yp[c] = __float2bfloat16(pv);
        if (c < D_SIZE) atomicAdd(&qacc[c], pv);
    }
    if (lane == 0) {
        g_rna[row]    = rna;
        g_diag[row]   = dot * rna * rnp;
        g_sumexp[row] = 0.f;
    }
    __syncthreads();
    for (int c = threadIdx.x; c < D_SIZE; c += 256)
        atomicAdd(&g_q[c], qacc[c]);
    if (blockIdx.x == 0 && threadIdx.x < 3) out[threadIdx.x] = 0.f;
}

// ---------------------------------------------------------------------------
// stage loader (128 threads): 128x32 A + 128x32 B bf16, 16B cp.async each
// ---------------------------------------------------------------------------
__device__ __forceinline__ void load_stage(uint32_t sbase, int m0, int n0,
                                           int k0, int tid) {
    const char* asrc = (const char*)g_Ab + ((size_t)m0 * KPAD + k0) * 2;
    const char* bsrc = (const char*)g_Pb + ((size_t)n0 * KPAD + k0) * 2;
    #pragma unroll
    for (int i = 0; i < 4; i++) {
        int seg = tid + i * 128, row = seg >> 2, g = seg & 3;
        cp16(sbase + row * ROWB + g * 16, asrc + (size_t)row * (KPAD * 2) + g * 16);
    }
    #pragma unroll
    for (int i = 0; i < 4; i++) {
        int seg = tid + i * 128, row = seg >> 2, g = seg & 3;
        cp16(sbase + BM * ROWB + row * ROWB + g * 16,
             bsrc + (size_t)row * (KPAD * 2) + g * 16);
    }
    asm volatile("cp.async.commit_group;" ::: "memory");
}

// ---------------------------------------------------------------------------
// main: 128x128 tile, 4 warps (64x64), BK=32, 4 stages, 2 stages per barrier
// ---------------------------------------------------------------------------
__global__ void __launch_bounds__(128) ntxent_hmma() {
    extern __shared__ char smem[];
    const uint32_t sbase = smem_u32(smem);

    const int tid  = threadIdx.x;
    const int lane = tid & 31;
    const int wid  = tid >> 5;
    const int wm   = wid >> 1;
    const int wn   = wid & 1;
    const int m0   = blockIdx.y * BM;
    const int n0   = blockIdx.x * BN;

    float acc[4][8][4];
    #pragma unroll
    for (int i = 0; i < 4; i++)
        #pragma unroll
        for (int j = 0; j < 8; j++)
            #pragma unroll
            for (int q = 0; q < 4; q++) acc[i][j][q] = 0.f;

    const int a_row  = lane & 15;
    const int a_koff = ((lane >> 4) & 1) * 16;
    const int b_n    = (lane & 7) | ((lane >> 1) & 8);
    const int b_koff = ((lane >> 3) & 1) * 16;
    const uint32_t aBase = sbase + (wm * 64 + a_row) * ROWB + a_koff;
    const uint32_t bBase = sbase + BM * ROWB + (wn * 64 + b_n) * ROWB + b_koff;

    // prologue: stages 0,1,2 in flight (one commit group each)
    load_stage(sbase + 0 * STAGE_BYTES, m0, n0, 0 * BK, tid);
    load_stage(sbase + 1 * STAGE_BYTES, m0, n0, 1 * BK, tid);
    load_stage(sbase + 2 * STAGE_BYTES, m0, n0, 2 * BK, tid);

    int lk = 3;                      // next BK-block index to load

    for (int it = 0; it < NHALF; it++) {
        // need stages 2it and 2it+1: in steady state 3 groups pending and
        // the needed two are the oldest -> wait_group 1. Last iter: drain.
        if (it < NHALF - 1) asm volatile("cp.async.wait_group 1;" ::: "memory");
        else                asm volatile("cp.async.wait_group 0;" ::: "memory");
        __syncthreads();

        const uint32_t base0 = (uint32_t)(((2 * it) & 3)) * STAGE_BYTES;

        #pragma unroll
        for (int half = 0; half < 2; half++) {
            const uint32_t sOff = base0 + (uint32_t)half * STAGE_BYTES;
            #pragma unroll
            for (int ks = 0; ks < 2; ks++) {
                const uint32_t koff = sOff + ks * 32;

                uint32_t afrag[4][4];
                #pragma unroll
                for (int mi = 0; mi < 4; mi++)
                    ldsm_x4(afrag[mi], aBase + koff + mi * (16 * ROWB));

                uint32_t bfrag[4][4];
                #pragma unroll
                for (int np = 0; np < 4; np++)
                    ldsm_x4(bfrag[np], bBase + koff + np * (16 * ROWB));

                #pragma unroll
                for (int mi = 0; mi < 4; mi++)
                    #pragma unroll
                    for (int np = 0; np < 4; np++) {
                        mma_bf16(acc[mi][np * 2 + 0], afrag[mi],
                                 bfrag[np][0], bfrag[np][1]);
                        mma_bf16(acc[mi][np * 2 + 1], afrag[mi],
                                 bfrag[np][2], bfrag[np][3]);
                    }
            }
        }

        // refill the two freed stages (lk%4 cycles through them)
        #pragma unroll
        for (int r = 0; r < 2; r++) {
            if (lk < NITER) {
                load_stage(sbase + (uint32_t)(lk & 3) * STAGE_BYTES,
                           m0, n0, lk * BK, tid);
                lk++;
            }
        }
    }

    // ---- epilogue: per-row sum of exp(4*S) ----
    float esum[8];
    #pragma unroll
    for (int q = 0; q < 8; q++) esum[q] = 0.f;

    #pragma unroll
    for (int mi = 0; mi < 4; mi++)
        #pragma unroll
        for (int nt = 0; nt < 8; nt++) {
            const float* cc = acc[mi][nt];
            esum[mi * 2 + 0] += __expf(INV_TEMP * cc[0]) + __expf(INV_TEMP * cc[1]);
            esum[mi * 2 + 1] += __expf(INV_TEMP * cc[2]) + __expf(INV_TEMP * cc[3]);
        }
    #pragma unroll
    for (int q = 0; q < 8; q++)
        #pragma unroll
        for (int o = 1; o < 4; o <<= 1)
            esum[q] += __shfl_xor_sync(0xffffffffu, esum[q], o);
    if ((lane & 3) == 0) {
        #pragma unroll
        for (int q = 0; q < 8; q++) {
            const int row = m0 + wm * 64 + (q >> 1) * 16 + (q & 1) * 8 + (lane >> 2);
            atomicAdd(&g_sumexp[row], esum[q]);
        }
    }
}

// ---------------------------------------------------------------------------
// finalize (R15 float2 version): rowsum fused; one warp per row
// ---------------------------------------------------------------------------
__global__ void __launch_bounds__(256) ntxent_finalize(const float* __restrict__ A,
                                                       float* __restrict__ out) {
    const int warp = threadIdx.x >> 5;
    const int lane = threadIdx.x & 31;
    const int row  = blockIdx.x * 8 + warp;

    const float2* ar2 = (const float2*)(A + (size_t)row * D_SIZE);
    const float2* q2  = (const float2*)g_q;
    float d0 = 0.f, d1 = 0.f;
    for (int c2 = lane; c2 < D2; c2 += 32) {
        float2 av = ar2[c2], qv = q2[c2];
        d0 = fmaf(av.x, qv.x, d0);
        d1 = fmaf(av.y, qv.y, d1);
    }
    float d = d0 + d1;
    #pragma unroll
    for (int o = 16; o; o >>= 1) d += __shfl_xor_sync(0xffffffffu, d, o);

    float loss = 0.f, pos = 0.f, neg = 0.f;
    if (lane == 0) {
        const float diag = g_diag[row];
        const float sumS = d * g_rna[row];
        loss = logf(g_sumexp[row]) - INV_TEMP * diag;
        pos  = diag;
        neg  = (sumS - diag) * (1.0f / (float)(B_SIZE - 1));
    }

    __shared__ float sl[8], sp[8], sn[8];
    if (lane == 0) { sl[warp] = loss; sp[warp] = pos; sn[warp] = neg; }
    __syncthreads();
    if (threadIdx.x == 0) {
        float tl = 0.f, tp = 0.f, tg = 0.f;
        #pragma unroll
        for (int w = 0; w < 8; w++) { tl += sl[w]; tp += sp[w]; tg += sn[w]; }
        const float invB = 1.0f / (float)B_SIZE;
        atomicAdd(out + 0, tl * invB);
        atomicAdd(out + 1, tp * invB);
        atomicAdd(out + 2, tg * invB);
    }
}

// ---------------------------------------------------------------------------
extern "C" void kernel_launch(void* const* d_in, const int* in_sizes, int n_in,
                              void* d_out, int out_size) {
    const float* A = (const float*)d_in[0];
    const float* P = (const float*)d_in[1];
    float* out = (float*)d_out;

    cudaFuncSetAttribute(ntxent_hmma,
                         cudaFuncAttributeMaxDynamicSharedMemorySize, SMEM_BYTES);

    ntxent_zeroq<<<1, 1024>>>();
    ntxent_prep<<<B_SIZE / 8, 256>>>(A, P, out);

    dim3 gg(B_SIZE / BN, B_SIZE / BM);   // (64, 64)
    ntxent_hmma<<<gg, 128, SMEM_BYTES>>>();

    ntxent_finalize<<<B_SIZE / 8, 256>>>(A, out);
}